// round 1
// baseline (speedup 1.0000x reference)
#include <cuda_runtime.h>
#include <cuda_bf16.h>
#include <limits.h>

#define TPB 256
#define MAX_BLOCKS 2048
#define NUM_CLASSES 80
#define CONF 0.25f

// Scratch for grid-level combine (static device globals — no allocation).
__device__ float        g_bS[MAX_BLOCKS];
__device__ int          g_bF[MAX_BLOCKS];
__device__ unsigned int g_ticket = 0;

// Segmented "first-fail prefix sum" monoid.
// State: f = global row index of first below-threshold row in the segment
//        (INT_MAX if none); s = sum of scores strictly before f (or the
//        whole-segment sum if f == INT_MAX).
// combine(A, B) with A covering earlier rows than B:
__device__ __forceinline__ void combine(int& f, float& s, int of, float os) {
    if (f == INT_MAX) { s += os; f = of; }
    // else: A already failed -> keep (f, s) unchanged.
}

__device__ __forceinline__ void warp_combine(int& f, float& s) {
    #pragma unroll
    for (int off = 16; off > 0; off >>= 1) {
        int   of = __shfl_down_sync(0xffffffffu, f, off);
        float os = __shfl_down_sync(0xffffffffu, s, off);
        combine(f, s, of, os);
    }
}

__global__ void yolo_prefix_kernel(const float* __restrict__ post,
                                   float* __restrict__ out,
                                   int K, int nblocks) {
    const int tid  = threadIdx.x;
    const int g    = blockIdx.x * TPB + tid;
    const int warp = tid >> 5;
    const int lane = tid & 31;

    // ---- Phase 1: per-row max + per-thread segment state ----
    int   f = INT_MAX;
    float s = 0.0f;
    if (g < K) {
        const float4* r = reinterpret_cast<const float4*>(post + (size_t)g * NUM_CLASSES);
        float m = -1.0e30f;
        #pragma unroll
        for (int i = 0; i < NUM_CLASSES / 4; i++) {
            float4 v = __ldg(r + i);
            m = fmaxf(m, fmaxf(fmaxf(v.x, v.y), fmaxf(v.z, v.w)));
        }
        if (m < CONF) { f = g; s = 0.0f; }
        else          { f = INT_MAX; s = m; }
    }

    // ---- Phase 2: ordered warp reduce (lane order == row order) ----
    warp_combine(f, s);

    __shared__ int   sf[TPB / 32];
    __shared__ float ss[TPB / 32];
    if (lane == 0) { sf[warp] = f; ss[warp] = s; }
    __syncthreads();

    // ---- Phase 3: block combine (warp order == row order) ----
    if (tid == 0) {
        int   bf = sf[0];
        float bs = ss[0];
        #pragma unroll
        for (int w = 1; w < TPB / 32; w++)
            combine(bf, bs, sf[w], ss[w]);
        g_bF[blockIdx.x] = bf;
        g_bS[blockIdx.x] = bs;
    }

    // ---- Phase 4: last-block grid finish (fenced ticket) ----
    __shared__ bool isLast;
    if (tid == 0) {
        __threadfence();
        unsigned int t = atomicAdd(&g_ticket, 1u);
        isLast = (t == (unsigned int)nblocks - 1u);
    }
    __syncthreads();

    if (isLast) {
        __threadfence();  // make all blocks' g_bF/g_bS visible
        // Each thread takes a contiguous chunk (chunk order == block order).
        const int per = (nblocks + TPB - 1) / TPB;
        int   cf = INT_MAX;
        float cs = 0.0f;
        const int start = tid * per;
        for (int j = start; j < start + per && j < nblocks; j++) {
            int   of = __ldcg(&g_bF[j]);
            float os = __ldcg(&g_bS[j]);
            combine(cf, cs, of, os);
        }
        warp_combine(cf, cs);
        if (lane == 0) { sf[warp] = cf; ss[warp] = cs; }
        __syncthreads();
        if (tid == 0) {
            int   rf = sf[0];
            float rs = ss[0];
            #pragma unroll
            for (int w = 1; w < TPB / 32; w++)
                combine(rf, rs, sf[w], ss[w]);
            out[0] = rs;
            __threadfence();
            g_ticket = 0;  // reset for deterministic graph replay
        }
    }
}

extern "C" void kernel_launch(void* const* d_in, const int* in_sizes, int n_in,
                              void* d_out, int out_size) {
    const float* post = (const float*)d_in[0];
    // d_in[1] (pre_post_boxes) is unused by the reference path.
    float* out = (float*)d_out;

    const int n_rows = in_sizes[0] / NUM_CLASSES;   // 262144
    const int K      = n_rows / 2;                  // ratio = 0.5 -> 131072

    int nblocks = (K + TPB - 1) / TPB;              // 512
    if (nblocks > MAX_BLOCKS) nblocks = MAX_BLOCKS; // safety (not hit here)

    yolo_prefix_kernel<<<nblocks, TPB>>>(post, out, K, nblocks);
}

// round 2
// speedup vs baseline: 1.0892x; 1.0892x over previous
#include <cuda_runtime.h>
#include <cuda_bf16.h>
#include <limits.h>

#define TPB 256
#define ROWS_PER_BLOCK 128
#define MAX_BLOCKS 4096
#define NUM_CLASSES 80
#define F4_PER_ROW 20            // 80 floats = 20 float4
#define SMEM_STRIDE 21           // padded row stride in float4 (84 floats)
#define CONF 0.25f

// Scratch for grid-level combine (static device globals — no allocation).
__device__ float        g_bS[MAX_BLOCKS];
__device__ int          g_bF[MAX_BLOCKS];
__device__ unsigned int g_ticket = 0;

// Segmented "first-fail prefix" monoid.
// f = global row index of first below-threshold row (INT_MAX if none);
// s = sum of row-maxes strictly before f (whole-segment sum if f==INT_MAX).
// Identity: (INT_MAX, 0). combine(A,B), A earlier than B:
__device__ __forceinline__ void combine(int& f, float& s, int of, float os) {
    if (f == INT_MAX) { s += os; f = of; }
}

__device__ __forceinline__ void warp_combine(int& f, float& s) {
    #pragma unroll
    for (int off = 16; off > 0; off >>= 1) {
        int   of = __shfl_down_sync(0xffffffffu, f, off);
        float os = __shfl_down_sync(0xffffffffu, s, off);
        combine(f, s, of, os);
    }
}

__global__ __launch_bounds__(TPB) void yolo_prefix_kernel(
        const float4* __restrict__ post4,
        float* __restrict__ out,
        int K, int nblocks) {
    __shared__ float4 tile[ROWS_PER_BLOCK * SMEM_STRIDE];   // 43008 B
    __shared__ int    sf[TPB / 32];
    __shared__ float  ss[TPB / 32];

    const int tid  = threadIdx.x;
    const int warp = tid >> 5;
    const int lane = tid & 31;
    const int row_base = blockIdx.x * ROWS_PER_BLOCK;

    // ---- Phase 1: coalesced stage of 128 rows (2560 float4) into smem ----
    // thread t loads float4 index t + 256*i within the tile: fully coalesced.
    {
        const size_t g4_base = (size_t)row_base * F4_PER_ROW;
        #pragma unroll
        for (int i = 0; i < (ROWS_PER_BLOCK * F4_PER_ROW) / TPB; i++) {  // 10 iters
            int q = tid + TPB * i;
            float4 v = __ldcs(post4 + g4_base + q);
            int r  = q / F4_PER_ROW;       // mul-shift
            int c4 = q - r * F4_PER_ROW;
            tile[r * SMEM_STRIDE + c4] = v;
        }
    }
    __syncthreads();

    // ---- Phase 2: 2 threads per row compute row max from smem ----
    const int r    = tid >> 1;             // local row 0..127
    const int half = tid & 1;              // which 10 float4s
    float m = -1.0e30f;
    {
        const float4* rp = &tile[r * SMEM_STRIDE + half * (F4_PER_ROW / 2)];
        #pragma unroll
        for (int j = 0; j < F4_PER_ROW / 2; j++) {          // 10 LDS.128
            float4 v = rp[j];
            m = fmaxf(m, fmaxf(fmaxf(v.x, v.y), fmaxf(v.z, v.w)));
        }
    }
    m = fmaxf(m, __shfl_xor_sync(0xffffffffu, m, 1));       // full row max

    // ---- Phase 3: build per-lane segment state (row order preserved) ----
    // Even lane 2r' carries row (row_base + r); odd lanes carry identity.
    int   f;
    float s;
    const int grow = row_base + r;
    if (half == 0 && grow < K) {
        if (m < CONF) { f = grow;   s = 0.0f; }
        else          { f = INT_MAX; s = m;   }
    } else {
        f = INT_MAX; s = 0.0f;                               // identity
    }

    // ---- Phase 4: ordered warp reduce (lane order == row order) ----
    warp_combine(f, s);
    if (lane == 0) { sf[warp] = f; ss[warp] = s; }
    __syncthreads();

    // ---- Phase 5: block combine (warp order == row order) ----
    if (tid == 0) {
        int   bf = sf[0];
        float bs = ss[0];
        #pragma unroll
        for (int w = 1; w < TPB / 32; w++)
            combine(bf, bs, sf[w], ss[w]);
        g_bF[blockIdx.x] = bf;
        g_bS[blockIdx.x] = bs;
    }

    // ---- Phase 6: last-block grid finish (fenced ticket) ----
    __shared__ bool isLast;
    if (tid == 0) {
        __threadfence();
        unsigned int t = atomicAdd(&g_ticket, 1u);
        isLast = (t == (unsigned int)nblocks - 1u);
    }
    __syncthreads();

    if (isLast) {
        __threadfence();  // make all blocks' partials visible
        const int per = (nblocks + TPB - 1) / TPB;
        int   cf = INT_MAX;
        float cs = 0.0f;
        const int start = tid * per;
        for (int j = start; j < start + per && j < nblocks; j++) {
            int   of = __ldcg(&g_bF[j]);
            float os = __ldcg(&g_bS[j]);
            combine(cf, cs, of, os);
        }
        warp_combine(cf, cs);
        if (lane == 0) { sf[warp] = cf; ss[warp] = cs; }
        __syncthreads();
        if (tid == 0) {
            int   rf = sf[0];
            float rs = ss[0];
            #pragma unroll
            for (int w = 1; w < TPB / 32; w++)
                combine(rf, rs, sf[w], ss[w]);
            out[0] = rs;
            __threadfence();
            g_ticket = 0;  // reset for deterministic graph replay
        }
    }
}

extern "C" void kernel_launch(void* const* d_in, const int* in_sizes, int n_in,
                              void* d_out, int out_size) {
    const float4* post4 = (const float4*)d_in[0];
    float* out = (float*)d_out;

    const int n_rows = in_sizes[0] / NUM_CLASSES;   // 262144
    const int K      = n_rows / 2;                  // ratio = 0.5 -> 131072

    int nblocks = (K + ROWS_PER_BLOCK - 1) / ROWS_PER_BLOCK;  // 1024
    if (nblocks > MAX_BLOCKS) nblocks = MAX_BLOCKS;           // safety

    yolo_prefix_kernel<<<nblocks, TPB>>>(post4, out, K, nblocks);
}

// round 6
// speedup vs baseline: 1.2543x; 1.1516x over previous
#include <cuda_runtime.h>
#include <cuda_bf16.h>
#include <cstdint>
#include <limits.h>

#define TPB 256
#define TILE_ROWS 64
#define F4_PER_ROW 20                       // 80 floats
#define F4_PER_TILE (TILE_ROWS * F4_PER_ROW)  // 1280 float4 = 20480 B
#define CP_PER_THREAD (F4_PER_TILE / TPB)     // 5
#define NUM_CLASSES 80
#define CONF 0.25f
#define MAX_TILES 8192
#define NSM 148
#define CTAS_PER_SM 5

// Per-tile partials + ticket (static device globals — no allocation).
__device__ float        g_tS[MAX_TILES];
__device__ int          g_tF[MAX_TILES];
__device__ unsigned int g_ticket = 0;

// Segmented "first-fail prefix" monoid.
// f = global row idx of first below-threshold row (INT_MAX if none);
// s = sum of row-maxes strictly before f (whole-segment sum if f==INT_MAX).
__device__ __forceinline__ void combine(int& f, float& s, int of, float os) {
    if (f == INT_MAX) { s += os; f = of; }
}

__device__ __forceinline__ void warp_combine(int& f, float& s) {
    #pragma unroll
    for (int off = 16; off > 0; off >>= 1) {
        int   of = __shfl_down_sync(0xffffffffu, f, off);
        float os = __shfl_down_sync(0xffffffffu, s, off);
        combine(f, s, of, os);
    }
}

__device__ __forceinline__ void cp_async16(unsigned int smem_addr, const void* gptr) {
    asm volatile("cp.async.cg.shared.global [%0], [%1], 16;"
                 :: "r"(smem_addr), "l"(gptr));
}
__device__ __forceinline__ void cp_commit() {
    asm volatile("cp.async.commit_group;");
}
__device__ __forceinline__ void cp_wait1() {
    asm volatile("cp.async.wait_group 1;");
}
__device__ __forceinline__ void cp_wait0() {
    asm volatile("cp.async.wait_group 0;");
}

__global__ __launch_bounds__(TPB) void yolo_prefix_kernel(
        const float4* __restrict__ post4,
        float* __restrict__ out,
        int K, int ntiles, int grid) {
    __shared__ float4 tile[2][F4_PER_TILE];   // 2 x 20480 B
    __shared__ int    sf[TPB / 32];
    __shared__ float  ss[TPB / 32];
    __shared__ bool   isLast;

    const int tid  = threadIdx.x;
    const int warp = tid >> 5;
    const int lane = tid & 31;

    unsigned int smem_base[2];
    smem_base[0] = (unsigned int)__cvta_generic_to_shared(&tile[0][0]);
    smem_base[1] = (unsigned int)__cvta_generic_to_shared(&tile[1][0]);

    // ---- Prologue: prefetch first tile ----
    const int t0 = blockIdx.x;
    if (t0 < ntiles) {
        const float4* g = post4 + (size_t)t0 * F4_PER_TILE;
        #pragma unroll
        for (int i = 0; i < CP_PER_THREAD; i++) {
            int q = tid + TPB * i;
            cp_async16(smem_base[0] + q * 16, g + q);
        }
        cp_commit();
    }

    int buf = 0;
    for (int t = t0; t < ntiles; t += grid) {
        // ---- Prefetch next tile into other buffer ----
        int tn = t + grid;
        if (tn < ntiles) {
            const float4* g = post4 + (size_t)tn * F4_PER_TILE;
            #pragma unroll
            for (int i = 0; i < CP_PER_THREAD; i++) {
                int q = tid + TPB * i;
                cp_async16(smem_base[buf ^ 1] + q * 16, g + q);
            }
        }
        cp_commit();
        cp_wait1();           // oldest group (current tile) complete
        __syncthreads();      // all threads' copies visible

        // ---- Compute: 4 threads per row, 5 LDS.128 each (conflict-free) ----
        const int r = tid >> 2;            // local row 0..63
        const int q = tid & 3;
        float m = -1.0e30f;
        {
            const float4* rp = &tile[buf][r * F4_PER_ROW + q * (F4_PER_ROW / 4)];
            #pragma unroll
            for (int j = 0; j < F4_PER_ROW / 4; j++) {
                float4 v = rp[j];
                m = fmaxf(m, fmaxf(fmaxf(v.x, v.y), fmaxf(v.z, v.w)));
            }
        }
        m = fmaxf(m, __shfl_xor_sync(0xffffffffu, m, 1));
        m = fmaxf(m, __shfl_xor_sync(0xffffffffu, m, 2));   // full row max

        // Per-lane segment state; only q==0 lanes carry a row, others identity.
        int   f = INT_MAX;
        float s = 0.0f;
        const int grow = t * TILE_ROWS + r;
        if (q == 0 && grow < K) {
            if (m < CONF) { f = grow; s = 0.0f; }
            else          { s = m; }
        }

        warp_combine(f, s);   // lane order == row order within warp
        if (lane == 0) { sf[warp] = f; ss[warp] = s; }
        __syncthreads();

        if (tid == 0) {
            int   bf = sf[0];
            float bs = ss[0];
            #pragma unroll
            for (int w = 1; w < TPB / 32; w++)
                combine(bf, bs, sf[w], ss[w]);
            g_tF[t] = bf;
            g_tS[t] = bs;
        }
        __syncthreads();      // done reading buf before it is refilled
        buf ^= 1;
    }
    cp_wait0();               // drain any speculative last prefetch

    // ---- Grid finish: ticket, last CTA combines all tiles in order ----
    if (tid == 0) {
        __threadfence();
        unsigned int tk = atomicAdd(&g_ticket, 1u);
        isLast = (tk == (unsigned int)grid - 1u);
    }
    __syncthreads();

    if (isLast) {
        __threadfence();
        const int per = (ntiles + TPB - 1) / TPB;
        int   cf = INT_MAX;
        float cs = 0.0f;
        const int start = tid * per;
        for (int j = start; j < start + per && j < ntiles; j++) {
            int   of = __ldcg(&g_tF[j]);
            float os = __ldcg(&g_tS[j]);
            combine(cf, cs, of, os);
        }
        warp_combine(cf, cs);
        if (lane == 0) { sf[warp] = cf; ss[warp] = cs; }
        __syncthreads();
        if (tid == 0) {
            int   rf = sf[0];
            float rs = ss[0];
            #pragma unroll
            for (int w = 1; w < TPB / 32; w++)
                combine(rf, rs, sf[w], ss[w]);
            out[0] = rs;
            __threadfence();
            g_ticket = 0;     // reset for deterministic graph replay
        }
    }
}

extern "C" void kernel_launch(void* const* d_in, const int* in_sizes, int n_in,
                              void* d_out, int out_size) {
    const float4* post4 = (const float4*)d_in[0];
    float* out = (float*)d_out;

    const int n_rows = in_sizes[0] / NUM_CLASSES;   // 262144
    const int K      = n_rows / 2;                  // ratio = 0.5 -> 131072

    int ntiles = (K + TILE_ROWS - 1) / TILE_ROWS;   // 2048
    if (ntiles > MAX_TILES) ntiles = MAX_TILES;

    int grid = NSM * CTAS_PER_SM;                   // 740 persistent CTAs
    if (grid > ntiles) grid = ntiles;

    yolo_prefix_kernel<<<grid, TPB>>>(post4, out, K, ntiles, grid);
}